// round 14
// baseline (speedup 1.0000x reference)
#include <cuda_runtime.h>
#include <cuda_fp16.h>

#define N 192
#define NV (N / 4)          // 48 float4 per x-row
#define NNN (N * N * N)
#define STEPS 20

// Ping buffer (pong is d_out).
__device__ float4 g_scratch4[NNN / 4];
// Interleaved fp16 maps, premultiplied by delta_t: per quad i,
// 16B record = {D0,D1,D2,D3,R0,R1,R2,R3} as halves.
__device__ uint4 g_DR[NNN / 4];

// ---- prepass: (D, rho) fp32 -> interleaved fp16 * delta_t ----
__global__ __launch_bounds__(256) void convert_maps_kernel(
    const float4* __restrict__ D4, const float4* __restrict__ R4,
    const float* __restrict__ dt_ptr, uint4* __restrict__ DR)
{
    const int i = blockIdx.x * blockDim.x + threadIdx.x;
    if (i >= NNN / 4) return;
    const float dt = dt_ptr[0] * (1.0f / (float)STEPS);
    const float4 d = D4[i];
    const float4 r = R4[i];
    uint4 o;
    *(__half2*)&o.x = __floats2half2_rn(d.x * dt, d.y * dt);
    *(__half2*)&o.y = __floats2half2_rn(d.z * dt, d.w * dt);
    *(__half2*)&o.z = __floats2half2_rn(r.x * dt, r.y * dt);
    *(__half2*)&o.w = __floats2half2_rn(r.z * dt, r.w * dt);
    DR[i] = o;
}

// DR load with L2 evict_last policy (read 20x across the run).
__device__ __forceinline__ uint4 ldg_el(const uint4* p) {
    uint4 v;
    asm volatile(
        "{\n\t"
        ".reg .b64 pol;\n\t"
        "createpolicy.fractional.L2::evict_last.b64 pol, 1.0;\n\t"
        "ld.global.nc.L2::cache_hint.v4.u32 {%0,%1,%2,%3}, [%4], pol;\n\t"
        "}"
        : "=r"(v.x), "=r"(v.y), "=r"(v.z), "=r"(v.w)
        : "l"(p));
    return v;
}

// c_next store with L2 evict_last policy (read exactly once, next step).
__device__ __forceinline__ void stg_el(float4* p, float4 v) {
    asm volatile(
        "{\n\t"
        ".reg .b64 pol;\n\t"
        "createpolicy.fractional.L2::evict_last.b64 pol, 1.0;\n\t"
        "st.global.L2::cache_hint.v4.f32 [%0], {%1,%2,%3,%4}, pol;\n\t"
        "}"
        :: "l"(p), "f"(v.x), "f"(v.y), "f"(v.z), "f"(v.w)
        : "memory");
}

// out = saturate(c + D'*lap + R'*(c - c^2)); D'/R' pre-scaled by dt.
__device__ __forceinline__ float upd(float c, float xl, float xr,
                                     float ym, float yp, float zm, float zp,
                                     float D, float R)
{
    float lap = fmaf(-6.f, c, (xl + xr) + (ym + yp) + (zm + zp));
    return __saturatef(fmaf(D, lap, fmaf(R, fmaf(-c, c, c), c)));
}

__device__ __forceinline__ float4 quad_upd(float4 c, float xl, float xr,
                                           float4 ym, float4 yp,
                                           float4 zm, float4 zp, uint4 dr)
{
    const float2 d01 = __half22float2(*(const __half2*)&dr.x);
    const float2 d23 = __half22float2(*(const __half2*)&dr.y);
    const float2 r01 = __half22float2(*(const __half2*)&dr.z);
    const float2 r23 = __half22float2(*(const __half2*)&dr.w);
    float4 o;
    o.x = upd(c.x, xl,  c.y, ym.x, yp.x, zm.x, zp.x, d01.x, r01.x);
    o.y = upd(c.y, c.x, c.z, ym.y, yp.y, zm.y, zp.y, d01.y, r01.y);
    o.z = upd(c.z, c.y, c.w, ym.z, yp.z, zm.z, zp.z, d23.x, r23.x);
    o.w = upd(c.w, c.z, xr,  ym.w, yp.w, zm.w, zp.w, d23.y, r23.y);
    return o;
}

// Each thread computes two quads stacked in y (rows y0, y0+1).
__global__ __launch_bounds__(192) void rd_step_kernel(
    const float4* __restrict__ src4,
    float4* __restrict__ dst4,
    const uint4* __restrict__ DR)
{
    const int tx = threadIdx.x;                                  // 0..47
    const int y0 = (blockIdx.y * blockDim.y + threadIdx.y) * 2;  // even, 0..190
    const int z  = blockIdx.z;                                   // 0..191
    const int idxA = (z * N + y0) * NV + tx;
    const int idxB = idxA + NV;

    const float* src = (const float*)src4;
    const float4 zero = make_float4(0.f, 0.f, 0.f, 0.f);

    // Wide loads, front-batched for MLP.
    const float4 cA = src4[idxA];
    const float4 cB = src4[idxB];
    const float4 ym = (y0 > 0)      ? src4[idxA - NV]     : zero;  // row y0-1
    const float4 yp = (y0 < N - 2)  ? src4[idxB + NV]     : zero;  // row y0+2
    const float4 zmA = (z > 0)      ? src4[idxA - NV * N] : zero;
    const float4 zmB = (z > 0)      ? src4[idxB - NV * N] : zero;
    const float4 zpA = (z < N - 1)  ? src4[idxA + NV * N] : zero;
    const float4 zpB = (z < N - 1)  ? src4[idxB + NV * N] : zero;
    const uint4 drA = ldg_el(DR + idxA);
    const uint4 drB = ldg_el(DR + idxB);
    const int baseA = idxA * 4, baseB = idxB * 4;
    const float lA = (tx > 0)      ? src[baseA - 1] : 0.f;
    const float rA = (tx < NV - 1) ? src[baseA + 4] : 0.f;
    const float lB = (tx > 0)      ? src[baseB - 1] : 0.f;
    const float rB = (tx < NV - 1) ? src[baseB + 4] : 0.f;

    // Row A: down-neighbor ym, up-neighbor cB. Row B: down cA, up yp.
    stg_el(dst4 + idxA, quad_upd(cA, lA, rA, ym, cB, zmA, zpA, drA));
    stg_el(dst4 + idxB, quad_upd(cB, lB, rB, cA, yp, zmB, zpB, drB));
}

extern "C" void kernel_launch(void* const* d_in, const int* in_sizes, int n_in,
                              void* d_out, int out_size)
{
    const float4* c_init = (const float4*)d_in[0];
    const float4* D_map  = (const float4*)d_in[1];
    const float4* rho    = (const float4*)d_in[2];
    const float*  dt     = (const float*)d_in[3];
    float4* out = (float4*)d_out;

    float4* scratch = nullptr;
    uint4* DR = nullptr;
    cudaGetSymbolAddress((void**)&scratch, g_scratch4);
    cudaGetSymbolAddress((void**)&DR, g_DR);

    convert_maps_kernel<<<(NNN / 4 + 255) / 256, 256>>>(D_map, rho, dt, DR);

    dim3 block(NV, 4, 1);       // 48 x 4 = 192 threads, 8 y-rows per block
    dim3 grid(1, N / 8, N);     // (1, 24, 192)

    const float4* src = c_init;
    for (int i = 0; i < STEPS; ++i) {
        float4* dst = (i & 1) ? out : scratch;
        rd_step_kernel<<<grid, block>>>(src, dst, DR);
        src = dst;
    }
}